// round 9
// baseline (speedup 1.0000x reference)
#include <cuda_runtime.h>

#define BATCH  2
#define NV     4096
#define NF     4096
#define IMG_H  256
#define IMG_W  256
#define ROWS_PB 4
#define THREADS (IMG_W * ROWS_PB)         // 1024
#define GRID    (BATCH * IMG_H / ROWS_PB) // 128 blocks (<=148 SMs: one wave)
#define SLICES  (GRID / BATCH)            // 64 producer slices per batch
#define TRIS_PER_SLICE (NF / SLICES)      // 64 triangles per block
#define POLL_MAX 20000                    // bounded: no deadlock possible

// Packed per-triangle screen coords (produced once per launch, chip-wide)
__device__ float4 g_triA[BATCH * NF];     // x0,y0,x1,y1
__device__ float4 g_triC[BATCH * NF];     // x2,y2,-,-
__device__ int    g_done[BATCH];          // producer slice counters (self-reset)
__device__ int    g_exit;                 // block exit counter (self-reset)

// ---------------------------------------------------------------------------
// One kernel, one wave. Phase A: each block transforms+packs its 64 triangles
// into global scratch (transform done ONCE chip-wide, 8k transforms total vs
// 400k in per-block schemes). Phase B: BOUNDED flag sync; on the (never-
// expected) timeout a block falls back to computing coverage on the fly from
// verts/faces with bit-identical arithmetic -> output is identical on either
// path, so the kernel is deterministic and deadlock-free under ANY scheduling.
// Phase C: per-pixel scan of packed triangles: 2 warp-uniform LDG (L1
// broadcast) + 12 FLOPs per tri, 4-wide OR groups, early exit; no barriers.
// Counters self-reset by the last exiting block.
// All expression orders match the reference (rel_err == 0).
// ---------------------------------------------------------------------------
__global__ void __launch_bounds__(THREADS) raster_once(
    const float* __restrict__ verts,   // [B,NV,3]
    const int*   __restrict__ faces,   // [B,NF,3]
    const float* __restrict__ Rm,      // [B,3,3]
    const float* __restrict__ Tm,      // [B,3]
    float*       __restrict__ out)     // [B,H,W,3]
{
    __shared__ int s_ok;

    const int rowsPerBatch = IMG_H / ROWS_PB;      // 64 blocks per batch
    int b     = blockIdx.x / rowsPerBatch;
    int slice = blockIdx.x - b * rowsPerBatch;     // 0..63
    int y0    = slice * ROWS_PB;
    int x     = threadIdx.x & (IMG_W - 1);
    int y     = y0 + (threadIdx.x >> 8);

    const int*   fb = faces + b * NF * 3;
    const float* vb = verts + b * NV * 3;

    // ---- VP rows (uniform loads; identical ordering to all passing rounds)
    const float* R = Rm + b * 9;
    const float* T = Tm + b * 3;

    float t0 = -((R[0] * T[0] + R[3] * T[1]) + R[6] * T[2]);
    float t1 = -((R[1] * T[0] + R[4] * T[1]) + R[7] * T[2]);
    float t2 = -((R[2] * T[0] + R[5] * T[1]) + R[8] * T[2]);

    const float f = 1.7320508075688772f;   // 1/tan(30 deg)

    float VP00 = f * R[0], VP01 = f * R[3], VP02 = f * R[6], VP03 = f * t0;
    float VP10 = f * R[1], VP11 = f * R[4], VP12 = f * R[7], VP13 = f * t1;
    float VP30 = -R[2],    VP31 = -R[5],    VP32 = -R[8],    VP33 = -t2;

    // transform one vertex index -> screen xy (reference expression order)
    auto xform = [&](int idx, float& ox, float& oy) {
        float a0 = __ldg(&vb[idx * 3 + 0]);
        float a1 = __ldg(&vb[idx * 3 + 1]);
        float a2 = __ldg(&vb[idx * 3 + 2]);
        float cx = ((a0 * VP00 + a1 * VP01) + a2 * VP02) + VP03;
        float cy = ((a0 * VP10 + a1 * VP11) + a2 * VP12) + VP13;
        float cw = ((a0 * VP30 + a1 * VP31) + a2 * VP32) + VP33;
        float w  = fmaxf(cw, 1e-8f);
        ox = cx / w; oy = cy / w;
    };

    // ================= Phase A: produce this block's 64 triangles ==========
    if (threadIdx.x < TRIS_PER_SLICE) {
        int t = slice * TRIS_PER_SLICE + threadIdx.x;
        int i0 = __ldg(&fb[t * 3 + 0]);
        int i1 = __ldg(&fb[t * 3 + 1]);
        int i2 = __ldg(&fb[t * 3 + 2]);
        float x0, y0f, x1, y1f, x2, y2f;
        xform(i0, x0, y0f);
        xform(i1, x1, y1f);
        xform(i2, x2, y2f);
        g_triA[b * NF + t] = make_float4(x0, y0f, x1, y1f);
        g_triC[b * NF + t] = make_float4(x2, y2f, 0.0f, 0.0f);
        __threadfence();
    }
    __syncthreads();

    // ================= Phase B: BOUNDED chip-wide flag sync ================
    if (threadIdx.x == 0) {
        atomicAdd(&g_done[b], 1);
        int ok = 0;
        for (int it = 0; it < POLL_MAX; ++it) {
            if (atomicAdd(&g_done[b], 0) >= SLICES) { ok = 1; break; }
            __nanosleep(32);
        }
        s_ok = ok;
        __threadfence();
    }
    __syncthreads();

    // ================= Phase C: per-pixel scan =============================
    float px = (((float)x + 0.5f) / (float)IMG_W) * 2.0f - 1.0f;
    float py = (((float)y + 0.5f) / (float)IMG_H) * 2.0f - 1.0f;

    float covered = 0.0f;

    if (s_ok) {
        // fast path: scan the packed list
        const float4* tA = g_triA + b * NF;
        const float4* tC = g_triC + b * NF;

        auto tri_inside = [&](int t) -> bool {
            float4 A = __ldg(&tA[t]);     // warp-uniform -> L1 broadcast
            float4 C = __ldg(&tC[t]);
            float e0 = (A.z - A.x) * (py - A.y) - (A.w - A.y) * (px - A.x);
            float e1 = (C.x - A.z) * (py - A.w) - (C.y - A.w) * (px - A.z);
            float e2 = (A.x - C.x) * (py - C.y) - (A.y - C.y) * (px - C.x);
            bool pos = (e0 >= 0.0f) & (e1 >= 0.0f) & (e2 >= 0.0f);
            bool neg = (e0 <= 0.0f) & (e1 <= 0.0f) & (e2 <= 0.0f);
            return pos | neg;
        };

        for (int t = 0; t < NF; t += 4) {
            bool hit = tri_inside(t)     | tri_inside(t + 1)
                     | tri_inside(t + 2) | tri_inside(t + 3);
            if (hit) { covered = 1.0f; break; }
        }
    } else {
        // fallback (never expected): compute on the fly, identical arithmetic
        for (int t = 0; t < NF; ++t) {
            int i0 = __ldg(&fb[t * 3 + 0]);
            int i1 = __ldg(&fb[t * 3 + 1]);
            int i2 = __ldg(&fb[t * 3 + 2]);
            float x0, y0f, x1, y1f, x2, y2f;
            xform(i0, x0, y0f);
            xform(i1, x1, y1f);
            xform(i2, x2, y2f);
            float e0 = (x1 - x0) * (py - y0f) - (y1f - y0f) * (px - x0);
            float e1 = (x2 - x1) * (py - y1f) - (y2f - y1f) * (px - x1);
            float e2 = (x0 - x2) * (py - y2f) - (y0f - y2f) * (px - x2);
            bool pos = (e0 >= 0.0f) & (e1 >= 0.0f) & (e2 >= 0.0f);
            bool neg = (e0 <= 0.0f) & (e1 <= 0.0f) & (e2 <= 0.0f);
            if (pos | neg) { covered = 1.0f; break; }
        }
    }

    int pix = (b * IMG_H + y) * IMG_W + x;
    float* o = out + (size_t)pix * 3;
    o[0] = covered;
    o[1] = covered;
    o[2] = covered;

    // ================= reset counters for next replay ======================
    __syncthreads();           // whole block finished
    if (threadIdx.x == 0) {
        int n = atomicAdd(&g_exit, 1);
        if (n == GRID - 1) {   // last block out: peers are past their polls
            g_done[0] = 0;
            g_done[1] = 0;
            __threadfence();
            g_exit = 0;
        }
    }
}

// ---------------------------------------------------------------------------
extern "C" void kernel_launch(void* const* d_in, const int* in_sizes, int n_in,
                              void* d_out, int out_size) {
    const float* verts = (const float*)d_in[0];   // [2,4096,3]
    const int*   faces = (const int*)  d_in[1];   // [2,4096,3]
    const float* Rm    = (const float*)d_in[2];   // [2,3,3]
    const float* Tm    = (const float*)d_in[3];   // [2,3]
    float* out = (float*)d_out;                   // [2,256,256,3]

    raster_once<<<GRID, THREADS>>>(verts, faces, Rm, Tm, out);
}

// round 10
// speedup vs baseline: 1.4760x; 1.4760x over previous
#include <cuda_runtime.h>

#define BATCH   2
#define NV      4096
#define NF      4096
#define IMG_H   256
#define IMG_W   256
#define ROWS_PB 4
#define THREADS (IMG_W * ROWS_PB)     // 1024
#define CHUNK   512                   // triangles staged per round
#define NVERT   (3 * CHUNK)           // 1536 vertex tasks per round

// ---------------------------------------------------------------------------
// Block = 4 image rows (1024 px / 1024 threads), grid = 128 (one block/SM).
// Stage 512 triangles per round into smem (1536 vertex tasks, 1.5/thread,
// chunk-0 indices prefetched before the VP setup so the two global misses
// overlap). P(a 512-triangle chunk lacks a screen-covering triangle) ~ 1e-7,
// so the chunk loop exits after ONE round essentially always; the full
// 8-round loop remains as the correctness fallback. Per-pixel test: smem
// broadcast reads, 4-wide OR groups (order-independent => value-identical to
// sequential early exit), early break. No global sync, no restaging in the
// expected path. All expression orders match the reference (rel_err == 0).
// ---------------------------------------------------------------------------
__global__ void __launch_bounds__(THREADS) raster_block(
    const float* __restrict__ verts,   // [B,NV,3]
    const int*   __restrict__ faces,   // [B,NF,3]
    const float* __restrict__ Rm,      // [B,3,3]
    const float* __restrict__ Tm,      // [B,3]
    float*       __restrict__ out)     // [B,H,W,3]
{
    __shared__ float2 sxy[NVERT];      // staged ndc (x,y) per corner, 12 KB

    const int rowsPerBatch = IMG_H / ROWS_PB;      // 64 blocks per batch
    int b  = blockIdx.x / rowsPerBatch;
    int y0 = (blockIdx.x - b * rowsPerBatch) * ROWS_PB;
    int x  = threadIdx.x & (IMG_W - 1);
    int y  = y0 + (threadIdx.x >> 8);

    const int*   fb = faces + b * NF * 3;
    const float* vb = verts + b * NV * 3;

    // ---- prefetch chunk-0 face indices (independent of R/T loads) ----
    int pidx0 = __ldg(&fb[threadIdx.x]);                       // task 0
    int pv1   = threadIdx.x + THREADS;                         // task 1
    int pidx1 = (pv1 < NVERT) ? __ldg(&fb[pv1]) : 0;

    // pixel center in ndc (same expression order as reference)
    float px = (((float)x + 0.5f) / (float)IMG_W) * 2.0f - 1.0f;
    float py = (((float)y + 0.5f) / (float)IMG_H) * 2.0f - 1.0f;

    // ---- VP rows for this batch (uniform loads; identical ordering) ----
    const float* R = Rm + b * 9;
    const float* T = Tm + b * 3;

    float t0 = -((R[0] * T[0] + R[3] * T[1]) + R[6] * T[2]);
    float t1 = -((R[1] * T[0] + R[4] * T[1]) + R[7] * T[2]);
    float t2 = -((R[2] * T[0] + R[5] * T[1]) + R[8] * T[2]);

    const float f = 1.7320508075688772f;   // 1/tan(30 deg)

    float VP00 = f * R[0], VP01 = f * R[3], VP02 = f * R[6], VP03 = f * t0;
    float VP10 = f * R[1], VP11 = f * R[4], VP12 = f * R[7], VP13 = f * t1;
    float VP30 = -R[2],    VP31 = -R[5],    VP32 = -R[8],    VP33 = -t2;

    // one vertex task: gather + transform + smem store (2 divides)
    auto stage_vertex = [&](int v, int idx) {
        float a0 = __ldg(&vb[idx * 3 + 0]);
        float a1 = __ldg(&vb[idx * 3 + 1]);
        float a2 = __ldg(&vb[idx * 3 + 2]);
        float cx = ((a0 * VP00 + a1 * VP01) + a2 * VP02) + VP03;
        float cy = ((a0 * VP10 + a1 * VP11) + a2 * VP12) + VP13;
        float cw = ((a0 * VP30 + a1 * VP31) + a2 * VP32) + VP33;
        float w  = fmaxf(cw, 1e-8f);
        sxy[v] = make_float2(cx / w, cy / w);
    };

    // inside-test for one staged triangle (expression order = reference)
    auto tri_inside = [&](int i) -> bool {
        float2 p0 = sxy[3 * i + 0];
        float2 p1 = sxy[3 * i + 1];
        float2 p2 = sxy[3 * i + 2];
        float e0 = (p1.x - p0.x) * (py - p0.y) - (p1.y - p0.y) * (px - p0.x);
        float e1 = (p2.x - p1.x) * (py - p1.y) - (p2.y - p1.y) * (px - p1.x);
        float e2 = (p0.x - p2.x) * (py - p2.y) - (p0.y - p2.y) * (px - p2.x);
        bool pos = (e0 >= 0.0f) & (e1 >= 0.0f) & (e2 >= 0.0f);
        bool neg = (e0 <= 0.0f) & (e1 <= 0.0f) & (e2 <= 0.0f);
        return pos | neg;
    };

    // test staged chunk, 4 triangles per iteration (OR is order-independent)
    auto test_chunk = [&](float covered) {
        if (covered == 0.0f) {
            for (int i = 0; i < CHUNK; i += 4) {
                bool hit = tri_inside(i)     | tri_inside(i + 1)
                         | tri_inside(i + 2) | tri_inside(i + 3);
                if (hit) { covered = 1.0f; break; }
            }
        }
        return covered;
    };

    float covered = 0.0f;

    // ---- chunk 0 (peeled; uses prefetched indices) ----
    stage_vertex(threadIdx.x, pidx0);
    if (pv1 < NVERT) stage_vertex(pv1, pidx1);
    __syncthreads();

    covered = test_chunk(covered);

    if (!__syncthreads_and(covered != 0.0f)) {
        // ---- remaining chunks (correctness fallback; ~never taken) ----
        for (int ct = 1; ct < NF / CHUNK; ++ct) {
            const int* fc = fb + ct * NVERT;
            for (int v = threadIdx.x; v < NVERT; v += THREADS) {
                int idx = __ldg(&fc[v]);
                stage_vertex(v, idx);
            }
            __syncthreads();

            covered = test_chunk(covered);

            if (__syncthreads_and(covered != 0.0f)) break;
        }
    }

    int pix = (b * IMG_H + y) * IMG_W + x;
    float* o = out + (size_t)pix * 3;
    o[0] = covered;
    o[1] = covered;
    o[2] = covered;
}

// ---------------------------------------------------------------------------
extern "C" void kernel_launch(void* const* d_in, const int* in_sizes, int n_in,
                              void* d_out, int out_size) {
    const float* verts = (const float*)d_in[0];   // [2,4096,3]
    const int*   faces = (const int*)  d_in[1];   // [2,4096,3]
    const float* Rm    = (const float*)d_in[2];   // [2,3,3]
    const float* Tm    = (const float*)d_in[3];   // [2,3]
    float* out = (float*)d_out;                   // [2,256,256,3]

    raster_block<<<BATCH * (IMG_H / ROWS_PB), THREADS>>>(verts, faces, Rm, Tm, out);
}